// round 8
// baseline (speedup 1.0000x reference)
#include <cuda_runtime.h>
#include <cuda_bf16.h>
#include <cstdint>

// ---------------- problem constants ----------------
#define NB   128
#define NPV  20
#define NPP  500
#define NVG  (NB*NPV)     // 2560
#define NPG  (NB*NPP)     // 64000
#define DD   256
#define FV   6
#define FP   8
#define DEG  8
#define EV   (NVG*DEG)
#define EP   (NPG*DEG)
#define CAP  64

// ---------------- static device scratch ----------------
__device__ float g_p_tmp [NPG*DD];            // h1 (p layer-1 output)
__device__ __nv_bfloat16 g_p_hi[NPG*DD];      // agg(h1) split
__device__ __nv_bfloat16 g_p_lo[NPG*DD];

__device__ float g_v_init[NVG*DD];
__device__ float g_v_tmp [NVG*DD];
__device__ float g_v_node[NVG*DD];
__device__ __nv_bfloat16 g_v_hi[NVG*DD];
__device__ __nv_bfloat16 g_v_lo[NVG*DD];

__device__ __nv_bfloat16 g_wtv2_hi[DD*DD]; __device__ __nv_bfloat16 g_wtv2_lo[DD*DD];
__device__ __nv_bfloat16 g_wtp2_hi[DD*DD]; __device__ __nv_bfloat16 g_wtp2_lo[DD*DD];

__device__ float g_Mp[9*DD];   // rows 0-7: Wi@W1 (zero-padded); row 8: bi@W1
__device__ float g_Mv[9*DD];

__device__ float g_p_agg8[NPG*8];
__device__ float g_p_s[NPG];
__device__ float g_v_agg8[NVG*8];
__device__ float g_v_s[NVG];

__device__ int   g_p_indeg[NPG];
__device__ int   g_v_indeg[NVG];
__device__ float g_p_dinv[NPG];
__device__ float g_v_dinv[NVG];
__device__ int   g_p_csr[NPG*CAP];
__device__ int   g_v_csr[NVG*CAP];

__device__ float g_pg_accum[NB*DD];  // fp32 pooled agg (atomic)
__device__ float g_vg[NB*DD];
__device__ float g_av2[NB*DD];       // combined per-graph additive vector

// ---------------- helpers ----------------
__device__ __forceinline__ uint32_t smem_u32(const void* p) {
    uint32_t a;
    asm("{ .reg .u64 t; cvta.to.shared.u64 t, %1; cvt.u32.u64 %0, t; }" : "=r"(a) : "l"(p));
    return a;
}
__device__ __forceinline__ void cpa16(uint32_t dst, const void* src) {
    asm volatile("cp.async.cg.shared.global [%0], [%1], 16;" :: "r"(dst), "l"(src) : "memory");
}
#define CPA_COMMIT() asm volatile("cp.async.commit_group;" ::: "memory")
#define CPA_WAIT0()  asm volatile("cp.async.wait_group 0;" ::: "memory")

#define MMA_OP(ACC, AH, B0, B1)                                                   \
    asm volatile(                                                                  \
        "mma.sync.aligned.m16n8k16.row.col.f32.bf16.bf16.f32 "                    \
        "{%0,%1,%2,%3}, {%4,%5,%6,%7}, {%8,%9}, {%0,%1,%2,%3};"                   \
        : "+f"((ACC)[0]), "+f"((ACC)[1]), "+f"((ACC)[2]), "+f"((ACC)[3])          \
        : "r"((AH)[0]), "r"((AH)[1]), "r"((AH)[2]), "r"((AH)[3]),                 \
          "r"(B0), "r"(B1))

// ---------------- setup kernels ----------------
// zero p_indeg, v_indeg, pg_accum in one launch
__global__ void zero_all(int* p_indeg, int* v_indeg, float* pgacc) {
    int i = blockIdx.x * blockDim.x + threadIdx.x;
    if (i < NPG) p_indeg[i] = 0;
    else if (i < NPG + NVG) v_indeg[i - NPG] = 0;
    else if (i < NPG + NVG + NB * DD) pgacc[i - NPG - NVG] = 0.0f;
}
__global__ void build_csr(const int* __restrict__ src, const int* __restrict__ dst,
                          int E, int* __restrict__ indeg, int* __restrict__ csr) {
    int e = blockIdx.x * blockDim.x + threadIdx.x;
    if (e >= E) return;
    int d = dst[e];
    int slot = atomicAdd(&indeg[d], 1);
    if (slot < CAP) csr[d * CAP + slot] = src[e];
}
__global__ void dinv_both(const int* __restrict__ p_indeg, const int* __restrict__ v_indeg,
                          float* __restrict__ p_dinv, float* __restrict__ v_dinv) {
    int i = blockIdx.x * blockDim.x + threadIdx.x;
    if (i < NPG) p_dinv[i] = rsqrtf((float)p_indeg[i] + 1.0f);
    else if (i < NPG + NVG) v_dinv[i - NPG] = rsqrtf((float)v_indeg[i - NPG] + 1.0f);
}

// M rows 0..7 = Wi@W1 (zero-padded); row 8 = bi@W1 ; grid 18 covers p (0-8) and v (9-17)
__global__ __launch_bounds__(256) void prep_M_both(
    const float* __restrict__ pWi, const float* __restrict__ pbi, const float* __restrict__ pW1,
    const float* __restrict__ vWi, const float* __restrict__ vbi, const float* __restrict__ vW1,
    float* __restrict__ Mp, float* __restrict__ Mv) {
    int blk = blockIdx.x, d = threadIdx.x;
    const float* Wi; const float* bi; const float* W1; float* M; int F, f;
    if (blk < 9) { Wi = pWi; bi = pbi; W1 = pW1; M = Mp; F = FP; f = blk; }
    else         { Wi = vWi; bi = vbi; W1 = vW1; M = Mv; F = FV; f = blk - 9; }
    float acc = 0.0f;
    if (f < 8) {
        if (f < F)
            for (int j = 0; j < DD; j++)
                acc = fmaf(__ldg(&Wi[f * DD + j]), __ldg(&W1[j * DD + d]), acc);
    } else {
        for (int j = 0; j < DD; j++)
            acc = fmaf(__ldg(&bi[j]), __ldg(&W1[j * DD + d]), acc);
    }
    M[f * DD + d] = acc;
}

// transpose + bf16 split both W2s; grid 512
__global__ __launch_bounds__(256) void prep_wt_both(
    const float* __restrict__ pW2, const float* __restrict__ vW2,
    __nv_bfloat16* __restrict__ phi, __nv_bfloat16* __restrict__ plo,
    __nv_bfloat16* __restrict__ vhi, __nv_bfloat16* __restrict__ vlo) {
    int blk = blockIdx.x, k = threadIdx.x;
    const float* W; __nv_bfloat16 *hi, *lo; int n;
    if (blk < DD) { W = pW2; hi = phi; lo = plo; n = blk; }
    else          { W = vW2; hi = vhi; lo = vlo; n = blk - DD; }
    float w = W[k * DD + n];
    __nv_bfloat16 h = __float2bfloat16_rn(w);
    hi[n * DD + k] = h;
    lo[n * DD + k] = __float2bfloat16_rn(w - __bfloat162float(h));
}

// v init emb (needed for av2)
__global__ __launch_bounds__(256) void init_emb_kernel(
    const float* __restrict__ x, const float* __restrict__ W, const float* __restrict__ b,
    float* __restrict__ out, int F) {
    int node = blockIdx.x, d = threadIdx.x;
    const float* xr = x + node * F;
    float acc = __ldg(&b[d]);
    #pragma unroll 8
    for (int k = 0; k < 8; k++)
        if (k < F) acc = fmaf(__ldg(&xr[k]), __ldg(&W[k * DD + d]), acc);
    out[node * DD + d] = acc;
}

// ---------------- layer 1: feature-space agg (both nets, one launch) -------------
__global__ __launch_bounds__(256) void agg8_both(
    const float* __restrict__ px, const float* __restrict__ vx,
    const int* __restrict__ p_csr, const int* __restrict__ v_csr,
    const int* __restrict__ p_indeg, const int* __restrict__ v_indeg,
    const float* __restrict__ p_dinv, const float* __restrict__ v_dinv,
    float* __restrict__ p_agg8, float* __restrict__ v_agg8,
    float* __restrict__ p_s, float* __restrict__ v_s) {
    int i = blockIdx.x * blockDim.x + threadIdx.x;
    const float* x; const int* csr; const int* indeg; const float* dinv;
    float* agg8; float* sv; int node, F;
    if (i < NPG) { x = px; csr = p_csr; indeg = p_indeg; dinv = p_dinv;
                   agg8 = p_agg8; sv = p_s; node = i; F = FP; }
    else if (i < NPG + NVG) { x = vx; csr = v_csr; indeg = v_indeg; dinv = v_dinv;
                   agg8 = v_agg8; sv = v_s; node = i - NPG; F = FV; }
    else return;
    int deg = indeg[node];
    int cnt = deg < CAP ? deg : CAP;
    float self = 1.0f / ((float)deg + 1.0f);
    float ddst = dinv[node];
    float a[8];
    #pragma unroll
    for (int f = 0; f < 8; f++) a[f] = 0.0f;
    if (F == 8) {
        float4 x0 = *(const float4*)(x + node * 8);
        float4 x1 = *(const float4*)(x + node * 8 + 4);
        a[0] = x0.x * self; a[1] = x0.y * self; a[2] = x0.z * self; a[3] = x0.w * self;
        a[4] = x1.x * self; a[5] = x1.y * self; a[6] = x1.z * self; a[7] = x1.w * self;
    } else {
        for (int f = 0; f < F; f++) a[f] = x[node * F + f] * self;
    }
    float ssum = self;
    const int* cp = csr + node * CAP;
    for (int e = 0; e < cnt; e++) {
        int src = cp[e];
        float c = ddst * dinv[src];
        ssum += c;
        if (F == 8) {
            float4 m0 = *(const float4*)(x + src * 8);
            float4 m1 = *(const float4*)(x + src * 8 + 4);
            a[0] = fmaf(c, m0.x, a[0]); a[1] = fmaf(c, m0.y, a[1]);
            a[2] = fmaf(c, m0.z, a[2]); a[3] = fmaf(c, m0.w, a[3]);
            a[4] = fmaf(c, m1.x, a[4]); a[5] = fmaf(c, m1.y, a[5]);
            a[6] = fmaf(c, m1.z, a[6]); a[7] = fmaf(c, m1.w, a[7]);
        } else {
            for (int f = 0; f < F; f++) a[f] = fmaf(c, x[src * F + f], a[f]);
        }
    }
    *(float4*)(agg8 + node * 8)     = make_float4(a[0], a[1], a[2], a[3]);
    *(float4*)(agg8 + node * 8 + 4) = make_float4(a[4], a[5], a[6], a[7]);
    sv[node] = ssum;
}

// h1 = relu(agg8 @ M[0:8] + s * M[8] + b1) ; blocks cover p then v
__global__ __launch_bounds__(256) void layer1_both(
    const float* __restrict__ p_agg8, const float* __restrict__ p_sv,
    const float* __restrict__ v_agg8, const float* __restrict__ v_sv,
    const float* __restrict__ Mp, const float* __restrict__ Mv,
    const float* __restrict__ pb1, const float* __restrict__ vb1,
    float* __restrict__ p_h1, float* __restrict__ v_h1) {
    int blk = blockIdx.x, d = threadIdx.x;
    const float* agg8; const float* sv; const float* M; const float* b1; float* h1; int node;
    if (blk < NPG) { agg8 = p_agg8; sv = p_sv; M = Mp; b1 = pb1; h1 = p_h1; node = blk; }
    else           { agg8 = v_agg8; sv = v_sv; M = Mv; b1 = vb1; h1 = v_h1; node = blk - NPG; }
    float a0 = __ldg(&agg8[node * 8 + 0]), a1 = __ldg(&agg8[node * 8 + 1]);
    float a2 = __ldg(&agg8[node * 8 + 2]), a3 = __ldg(&agg8[node * 8 + 3]);
    float a4 = __ldg(&agg8[node * 8 + 4]), a5 = __ldg(&agg8[node * 8 + 5]);
    float a6 = __ldg(&agg8[node * 8 + 6]), a7 = __ldg(&agg8[node * 8 + 7]);
    float ss = __ldg(&sv[node]);
    float acc = __ldg(&b1[d]) + ss * __ldg(&M[8 * DD + d]);
    acc = fmaf(a0, __ldg(&M[0 * DD + d]), acc);
    acc = fmaf(a1, __ldg(&M[1 * DD + d]), acc);
    acc = fmaf(a2, __ldg(&M[2 * DD + d]), acc);
    acc = fmaf(a3, __ldg(&M[3 * DD + d]), acc);
    acc = fmaf(a4, __ldg(&M[4 * DD + d]), acc);
    acc = fmaf(a5, __ldg(&M[5 * DD + d]), acc);
    acc = fmaf(a6, __ldg(&M[6 * DD + d]), acc);
    acc = fmaf(a7, __ldg(&M[7 * DD + d]), acc);
    h1[node * DD + d] = fmaxf(acc, 0.0f);
}

// ---------------- 256-dim aggregation -> bf16 split (+optional graph pooling) ----
__global__ __launch_bounds__(256) void gcn_agg(
    const float* __restrict__ h, const int* __restrict__ csr, const int* __restrict__ indeg,
    const float* __restrict__ dinv, __nv_bfloat16* __restrict__ out_hi,
    __nv_bfloat16* __restrict__ out_lo, float* __restrict__ pgacc, int n_nodes) {
    __shared__ float red[8][DD];
    int warp = threadIdx.x >> 5;
    int lane = threadIdx.x & 31;
    int node = blockIdx.x * 8 + warp;
    int d0 = lane * 8;
    float4 acc0 = make_float4(0.f, 0.f, 0.f, 0.f), acc1 = acc0;

    if (node < n_nodes) {
        int deg = indeg[node];
        int cnt = deg < CAP ? deg : CAP;
        float self = 1.0f / ((float)deg + 1.0f);
        float ddst = dinv[node];
        const float* hn = h + node * DD + d0;
        float4 s0 = *(const float4*)hn;
        float4 s1 = *(const float4*)(hn + 4);
        acc0 = make_float4(s0.x * self, s0.y * self, s0.z * self, s0.w * self);
        acc1 = make_float4(s1.x * self, s1.y * self, s1.z * self, s1.w * self);
        const int* cp = csr + node * CAP;
        for (int e = 0; e < cnt; e++) {
            int src = cp[e];
            float c = ddst * dinv[src];
            const float* hs = h + src * DD + d0;
            float4 m0 = *(const float4*)hs;
            float4 m1 = *(const float4*)(hs + 4);
            acc0.x = fmaf(c, m0.x, acc0.x); acc0.y = fmaf(c, m0.y, acc0.y);
            acc0.z = fmaf(c, m0.z, acc0.z); acc0.w = fmaf(c, m0.w, acc0.w);
            acc1.x = fmaf(c, m1.x, acc1.x); acc1.y = fmaf(c, m1.y, acc1.y);
            acc1.z = fmaf(c, m1.z, acc1.z); acc1.w = fmaf(c, m1.w, acc1.w);
        }
        int base = node * DD + d0;
        float v[8] = {acc0.x, acc0.y, acc0.z, acc0.w, acc1.x, acc1.y, acc1.z, acc1.w};
        uint32_t hw[4], lw[4];
        #pragma unroll
        for (int q = 0; q < 4; q++) {
            __nv_bfloat16 h0 = __float2bfloat16_rn(v[q * 2]);
            __nv_bfloat16 h1v = __float2bfloat16_rn(v[q * 2 + 1]);
            __nv_bfloat16 l0 = __float2bfloat16_rn(v[q * 2] - __bfloat162float(h0));
            __nv_bfloat16 l1 = __float2bfloat16_rn(v[q * 2 + 1] - __bfloat162float(h1v));
            __nv_bfloat162 hp = __nv_bfloat162(h0, h1v);
            __nv_bfloat162 lp = __nv_bfloat162(l0, l1);
            hw[q] = *(uint32_t*)&hp;
            lw[q] = *(uint32_t*)&lp;
        }
        *(uint4*)(out_hi + base) = make_uint4(hw[0], hw[1], hw[2], hw[3]);
        *(uint4*)(out_lo + base) = make_uint4(lw[0], lw[1], lw[2], lw[3]);
    }
    if (!pgacc) return;

    // per-block graph pooling of the fp32 agg vectors
    *(float4*)&red[warp][d0]     = acc0;
    *(float4*)&red[warp][d0 + 4] = acc1;
    __syncthreads();
    int d = threadIdx.x;   // channel
    int node0 = blockIdx.x * 8;
    int g0 = node0 / NPP;
    float s0 = 0.f, s1 = 0.f;
    int g1 = (node0 + 7) / NPP;    // at most g0+1
    #pragma unroll
    for (int i = 0; i < 8; i++) {
        int nd = node0 + i;
        float val = red[i][d];
        if (nd / NPP == g0) s0 += val; else s1 += val;
    }
    atomicAdd(&pgacc[g0 * DD + d], s0);
    if (g1 != g0) atomicAdd(&pgacc[g1 * DD + d], s1);
}

// ---------------- smem-staged bf16-split GEMM (plain: for v net) -------------
#define KC 32
#define APITCH 80
#define PIECE (128*APITCH)
#define STAGE_BYTES (4*PIECE)
#define GEMM_SMEM (2*STAGE_BYTES)

#define GEMM_PRE()                                                                 \
    extern __shared__ char sm[];                                                   \
    uint32_t sb = smem_u32(sm);                                                    \
    int tid = threadIdx.x;                                                         \
    int wid = tid >> 5, lane = tid & 31;                                           \
    int g = lane >> 2, t = lane & 3;                                               \
    int warp_m = wid & 3, warp_n = wid >> 2;                                       \
    int row0 = blockIdx.y * 128;                                                   \
    int col0 = blockIdx.x * 128;                                                   \
    float acc[2][8][4];                                                            \
    _Pragma("unroll")                                                              \
    for (int s = 0; s < 2; s++)                                                    \
        _Pragma("unroll")                                                          \
        for (int n = 0; n < 8; n++)                                                \
            _Pragma("unroll")                                                      \
            for (int q = 0; q < 4; q++) acc[s][n][q] = 0.0f;                       \
    int r0i = (tid + 0) >> 2,  c0i = (tid + 0) & 3;                                \
    int r1i = (tid + 256) >> 2, c1i = (tid + 256) & 3;                             \
    auto stage_load = [&](int st) {                                                \
        uint32_t base = sb + (st & 1) * STAGE_BYTES;                               \
        int kc0 = st * KC;                                                         \
        {                                                                          \
            uint32_t d0 = base + r0i * APITCH + c0i * 16;                          \
            size_t ga = (size_t)(row0 + r0i) * DD + kc0 + c0i * 8;                 \
            size_t gb = (size_t)(col0 + r0i) * DD + kc0 + c0i * 8;                 \
            cpa16(d0,           A_hi + ga);                                        \
            cpa16(d0 + PIECE,   A_lo + ga);                                        \
            cpa16(d0 + 2*PIECE, Bt_hi + gb);                                       \
            cpa16(d0 + 3*PIECE, Bt_lo + gb);                                       \
        }                                                                          \
        {                                                                          \
            uint32_t d0 = base + r1i * APITCH + c1i * 16;                          \
            size_t ga = (size_t)(row0 + r1i) * DD + kc0 + c1i * 8;                 \
            size_t gb = (size_t)(col0 + r1i) * DD + kc0 + c1i * 8;                 \
            cpa16(d0,           A_hi + ga);                                        \
            cpa16(d0 + PIECE,   A_lo + ga);                                        \
            cpa16(d0 + 2*PIECE, Bt_hi + gb);                                       \
            cpa16(d0 + 3*PIECE, Bt_lo + gb);                                       \
        }                                                                          \
        CPA_COMMIT();                                                              \
    };                                                                             \
    stage_load(0);                                                                 \
    CPA_WAIT0();                                                                   \
    __syncthreads();                                                               \
    for (int st = 0; st < DD / KC; st++) {                                         \
        if (st + 1 < DD / KC) stage_load(st + 1);                                  \
        const char* cur = sm + (st & 1) * STAGE_BYTES;                             \
        _Pragma("unroll")                                                          \
        for (int kk = 0; kk < 2; kk++) {                                           \
            int kb = (kk * 16 + t * 2) * 2;                                        \
            uint32_t ah[2][4], al[2][4];                                           \
            _Pragma("unroll")                                                      \
            for (int s = 0; s < 2; s++) {                                          \
                const char* pa = cur + (warp_m * 32 + s * 16 + g) * APITCH + kb;   \
                ah[s][0] = *(const uint32_t*)pa;                                   \
                ah[s][1] = *(const uint32_t*)(pa + 8 * APITCH);                    \
                ah[s][2] = *(const uint32_t*)(pa + 16);                            \
                ah[s][3] = *(const uint32_t*)(pa + 8 * APITCH + 16);               \
                const char* pl = pa + PIECE;                                       \
                al[s][0] = *(const uint32_t*)pl;                                   \
                al[s][1] = *(const uint32_t*)(pl + 8 * APITCH);                    \
                al[s][2] = *(const uint32_t*)(pl + 16);                            \
                al[s][3] = *(const uint32_t*)(pl + 8 * APITCH + 16);               \
            }                                                                      \
            _Pragma("unroll")                                                      \
            for (int nt = 0; nt < 8; nt++) {                                       \
                const char* pb = cur + 2 * PIECE + (warp_n * 64 + nt * 8 + g) * APITCH + kb; \
                uint32_t bh0 = *(const uint32_t*)pb;                               \
                uint32_t bh1 = *(const uint32_t*)(pb + 16);                        \
                const char* pbl = pb + PIECE;                                      \
                uint32_t bl0 = *(const uint32_t*)pbl;                              \
                uint32_t bl1 = *(const uint32_t*)(pbl + 16);                       \
                _Pragma("unroll")                                                  \
                for (int s = 0; s < 2; s++) {                                      \
                    MMA_OP(acc[s][nt], ah[s], bh0, bh1);                           \
                    MMA_OP(acc[s][nt], ah[s], bl0, bl1);                           \
                    MMA_OP(acc[s][nt], al[s], bh0, bh1);                           \
                }                                                                  \
            }                                                                      \
        }                                                                          \
        CPA_WAIT0();                                                               \
        __syncthreads();                                                           \
    }

__global__ void __launch_bounds__(256, 2) gemm_smem(
    const __nv_bfloat16* __restrict__ A_hi, const __nv_bfloat16* __restrict__ A_lo,
    const __nv_bfloat16* __restrict__ Bt_hi, const __nv_bfloat16* __restrict__ Bt_lo,
    const float* __restrict__ bias, float* __restrict__ C) {
    GEMM_PRE()
    #pragma unroll
    for (int s = 0; s < 2; s++) {
        int r = row0 + warp_m * 32 + s * 16 + g;
        #pragma unroll
        for (int nt = 0; nt < 8; nt++) {
            int c = col0 + warp_n * 64 + nt * 8 + t * 2;
            float bx = __ldg(&bias[c]), by = __ldg(&bias[c + 1]);
            *(float2*)(C + r * DD + c)       = make_float2(acc[s][nt][0] + bx, acc[s][nt][1] + by);
            *(float2*)(C + (r + 8) * DD + c) = make_float2(acc[s][nt][2] + bx, acc[s][nt][3] + by);
        }
    }
}

// p-net GEMM with fully fused output epilogue:
// out[r,c] = acc + av2[b(r),c] + sum_k px[r,k]*Wi[k,c]
__global__ void __launch_bounds__(256, 2) gemm_fused_out(
    const __nv_bfloat16* __restrict__ A_hi, const __nv_bfloat16* __restrict__ A_lo,
    const __nv_bfloat16* __restrict__ Bt_hi, const __nv_bfloat16* __restrict__ Bt_lo,
    const float* __restrict__ av2, const float* __restrict__ px,
    const float* __restrict__ Wi, float* __restrict__ Cout) {
    GEMM_PRE()
    #pragma unroll
    for (int s = 0; s < 2; s++) {
        #pragma unroll
        for (int half = 0; half < 2; half++) {
            int rr = row0 + warp_m * 32 + s * 16 + g + half * 8;
            int bg = rr / NPP;
            const float* xr = px + rr * FP;
            float xv[8];
            #pragma unroll
            for (int k = 0; k < 8; k++) xv[k] = __ldg(&xr[k]);
            #pragma unroll
            for (int nt = 0; nt < 8; nt++) {
                int c = col0 + warp_n * 64 + nt * 8 + t * 2;
                float a0 = acc[s][nt][half * 2 + 0];
                float a1 = acc[s][nt][half * 2 + 1];
                float v0 = __ldg(&av2[bg * DD + c]);
                float v1 = __ldg(&av2[bg * DD + c + 1]);
                float p0 = 0.f, p1 = 0.f;
                #pragma unroll
                for (int k = 0; k < 8; k++) {
                    float2 w = *(const float2*)(Wi + k * DD + c);
                    p0 = fmaf(xv[k], w.x, p0);
                    p1 = fmaf(xv[k], w.y, p1);
                }
                *(float2*)(Cout + (size_t)rr * DD + c) = make_float2(a0 + v0 + p0, a1 + v1 + p1);
            }
        }
    }
}

// ---------------- pooling / combine ----------------
__global__ __launch_bounds__(256) void pool_v_kernel(
    const float* __restrict__ node_emb, float* __restrict__ g) {
    int b = blockIdx.x, d = threadIdx.x;
    const float* p = node_emb + (size_t)b * NPV * DD + d;
    float s = 0.f;
    #pragma unroll
    for (int i = 0; i < NPV; i++) s += p[i * DD];
    g[b * DD + d] = s * (1.0f / NPV);
}

// av2[b,d] = (pg_accum[b]/NPP)@W2[d] + 2*b2[d] + bi[d] + 2*vg + v_node[cid] + v_init[cid]
__global__ __launch_bounds__(256) void pg_addvec(
    const float* __restrict__ pgacc, const float* __restrict__ W2,
    const float* __restrict__ p_b2, const float* __restrict__ p_bi,
    const float* __restrict__ vg, const float* __restrict__ v_node,
    const float* __restrict__ v_init, const int* __restrict__ curr,
    float* __restrict__ av2) {
    int b = blockIdx.x, d = threadIdx.x;
    __shared__ float pa[DD];
    pa[d] = pgacc[b * DD + d] * (1.0f / NPP);
    __syncthreads();
    float acc = 0.f;
    #pragma unroll 8
    for (int k = 0; k < DD; k++)
        acc = fmaf(pa[k], __ldg(&W2[k * DD + d]), acc);
    int cid = curr[b];
    int vi = (b * NPV + cid) * DD + d;
    av2[b * DD + d] = acc + 2.0f * __ldg(&p_b2[d]) + __ldg(&p_bi[d])
                    + 2.0f * vg[b * DD + d] + v_node[vi] + v_init[vi];
}

// ---------------- host launch ----------------
static inline void* sym(const void* s) {
    void* p = nullptr;
    cudaGetSymbolAddress(&p, s);
    return p;
}

extern "C" void kernel_launch(void* const* d_in, const int* in_sizes, int n_in,
                              void* d_out, int out_size) {
    const float* v_x     = (const float*)d_in[0];
    const float* p_x     = (const float*)d_in[1];
    const int*   v_src   = (const int*)d_in[2];
    const int*   v_dst   = (const int*)d_in[3];
    const int*   p_src   = (const int*)d_in[4];
    const int*   p_dst   = (const int*)d_in[5];
    const int*   curr    = (const int*)d_in[8];
    const float* v_initW = (const float*)d_in[9];
    const float* v_initb = (const float*)d_in[10];
    const float* v_W1    = (const float*)d_in[11];
    const float* v_b1    = (const float*)d_in[12];
    const float* v_W2    = (const float*)d_in[13];
    const float* v_b2    = (const float*)d_in[14];
    const float* p_initW = (const float*)d_in[15];
    const float* p_initb = (const float*)d_in[16];
    const float* p_W1    = (const float*)d_in[17];
    const float* p_b1    = (const float*)d_in[18];
    const float* p_W2    = (const float*)d_in[19];
    const float* p_b2    = (const float*)d_in[20];
    float* out = (float*)d_out;

    float* p_tmp  = (float*)sym(g_p_tmp);
    __nv_bfloat16* p_hi = (__nv_bfloat16*)sym(g_p_hi);
    __nv_bfloat16* p_lo = (__nv_bfloat16*)sym(g_p_lo);
    float* v_init = (float*)sym(g_v_init);
    float* v_tmp  = (float*)sym(g_v_tmp);
    float* v_node = (float*)sym(g_v_node);
    __nv_bfloat16* v_hi = (__nv_bfloat16*)sym(g_v_hi);
    __nv_bfloat16* v_lo = (__nv_bfloat16*)sym(g_v_lo);
    __nv_bfloat16* wtv2h = (__nv_bfloat16*)sym(g_wtv2_hi);
    __nv_bfloat16* wtv2l = (__nv_bfloat16*)sym(g_wtv2_lo);
    __nv_bfloat16* wtp2h = (__nv_bfloat16*)sym(g_wtp2_hi);
    __nv_bfloat16* wtp2l = (__nv_bfloat16*)sym(g_wtp2_lo);
    float* Mp = (float*)sym(g_Mp);
    float* Mv = (float*)sym(g_Mv);
    float* p_agg8 = (float*)sym(g_p_agg8);
    float* p_s    = (float*)sym(g_p_s);
    float* v_agg8 = (float*)sym(g_v_agg8);
    float* v_s    = (float*)sym(g_v_s);
    int* p_indeg  = (int*)sym(g_p_indeg);
    int* v_indeg  = (int*)sym(g_v_indeg);
    float* p_dinv = (float*)sym(g_p_dinv);
    float* v_dinv = (float*)sym(g_v_dinv);
    int* p_csr    = (int*)sym(g_p_csr);
    int* v_csr    = (int*)sym(g_v_csr);
    float* pgacc  = (float*)sym(g_pg_accum);
    float* vg     = (float*)sym(g_vg);
    float* av2    = (float*)sym(g_av2);

    cudaFuncSetAttribute(gemm_smem, cudaFuncAttributeMaxDynamicSharedMemorySize, GEMM_SMEM);
    cudaFuncSetAttribute(gemm_fused_out, cudaFuncAttributeMaxDynamicSharedMemorySize, GEMM_SMEM);

    // 1. zero indeg arrays + pg accumulator
    zero_all<<<(NPG + NVG + NB * DD + 255) / 256, 256>>>(p_indeg, v_indeg, pgacc);
    // 2-3. CSR
    build_csr<<<(EV + 255) / 256, 256>>>(v_src, v_dst, EV, v_indeg, v_csr);
    build_csr<<<(EP + 255) / 256, 256>>>(p_src, p_dst, EP, p_indeg, p_csr);
    // 4. dinv
    dinv_both<<<(NPG + NVG + 255) / 256, 256>>>(p_indeg, v_indeg, p_dinv, v_dinv);
    // 5-6. weight prep
    prep_M_both<<<18, 256>>>(p_initW, p_initb, p_W1, v_initW, v_initb, v_W1, Mp, Mv);
    prep_wt_both<<<512, 256>>>(p_W2, v_W2, wtp2h, wtp2l, wtv2h, wtv2l);
    // 7. v init emb
    init_emb_kernel<<<NVG, 256>>>(v_x, v_initW, v_initb, v_init, FV);
    // 8-9. layer 1 both nets
    agg8_both<<<(NPG + NVG + 255) / 256, 256>>>(p_x, v_x, p_csr, v_csr, p_indeg, v_indeg,
                                                p_dinv, v_dinv, p_agg8, v_agg8, p_s, v_s);
    layer1_both<<<NPG + NVG, 256>>>(p_agg8, p_s, v_agg8, v_s, Mp, Mv, p_b1, v_b1, p_tmp, v_tmp);
    // 10-12. v net layer 2 + pooling
    gcn_agg<<<(NVG + 7) / 8, 256>>>(v_tmp, v_csr, v_indeg, v_dinv, v_hi, v_lo, nullptr, NVG);
    {
        dim3 gv(2, NVG / 128);
        gemm_smem<<<gv, 256, GEMM_SMEM>>>(v_hi, v_lo, wtv2h, wtv2l, v_b2, v_node);
    }
    pool_v_kernel<<<NB, 256>>>(v_node, vg);
    // 13. p agg (+ fused graph pooling)
    gcn_agg<<<(NPG + 7) / 8, 256>>>(p_tmp, p_csr, p_indeg, p_dinv, p_hi, p_lo, pgacc, NPG);
    // 14. combined additive vector
    pg_addvec<<<NB, 256>>>(pgacc, p_W2, p_b2, p_initb, vg, v_node, v_init, curr, av2);
    // 15. p GEMM with fused final output
    {
        dim3 gp(2, NPG / 128);
        gemm_fused_out<<<gp, 256, GEMM_SMEM>>>(p_hi, p_lo, wtp2h, wtp2l, av2, p_x, p_initW, out);
    }
}